// round 5
// baseline (speedup 1.0000x reference)
#include <cuda_runtime.h>

#define D_FEAT 64

__device__ int g_row_ptr[100001];

// Kernel A: row_ptr[r] = lower_bound(row, E, r).
__global__ void build_row_ptr(const int* __restrict__ row, int n, int E) {
    int r = blockIdx.x * blockDim.x + threadIdx.x;
    if (r > n) return;
    int lo = 0, hi = E;
    while (lo < hi) {
        int mid = (lo + hi) >> 1;
        if (__ldg(&row[mid]) < r) lo = mid + 1;
        else hi = mid;
    }
    g_row_ptr[r] = lo;
}

// Kernel B: TWO rows per warp, lane owns features {2l,2l+1} (float2).
// Joint main loop runs both rows' quads together: 8 independent x-gathers in
// flight per warp (double the MLP of one-row-per-warp). Metadata via scalar
// broadcast __ldg (uniform address; wavefront count proven non-binding).
__global__ void spmm_mean_2rows(const float* __restrict__ x,
                                const float* __restrict__ vals,
                                const int* __restrict__ col,
                                float* __restrict__ out,
                                int n) {
    int warp_id = (blockIdx.x * blockDim.x + threadIdx.x) >> 5;
    int lane = threadIdx.x & 31;

    int r0 = 2 * warp_id;
    int r1 = r0 + 1;
    if (r0 >= n) return;
    bool has1 = (r1 < n);

    int s0 = g_row_ptr[r0];
    int e0 = g_row_ptr[r0 + 1];
    int s1 = has1 ? g_row_ptr[r1] : 0;
    int e1 = has1 ? g_row_ptr[r1 + 1] : 0;

    const float* xb = x + 2 * lane;
    float2 acc0 = make_float2(0.f, 0.f);
    float2 acc1 = make_float2(0.f, 0.f);

    int i0 = s0, i1 = s1;

    // Joint main loop: 4 edges from each row -> 8 gathers in flight.
    while (i0 + 4 <= e0 && i1 + 4 <= e1) {
        int   ca0 = __ldg(&col[i0 + 0]), ca1 = __ldg(&col[i0 + 1]);
        int   ca2 = __ldg(&col[i0 + 2]), ca3 = __ldg(&col[i0 + 3]);
        int   cb0 = __ldg(&col[i1 + 0]), cb1 = __ldg(&col[i1 + 1]);
        int   cb2 = __ldg(&col[i1 + 2]), cb3 = __ldg(&col[i1 + 3]);
        float va0 = __ldg(&vals[i0 + 0]), va1 = __ldg(&vals[i0 + 1]);
        float va2 = __ldg(&vals[i0 + 2]), va3 = __ldg(&vals[i0 + 3]);
        float vb0 = __ldg(&vals[i1 + 0]), vb1 = __ldg(&vals[i1 + 1]);
        float vb2 = __ldg(&vals[i1 + 2]), vb3 = __ldg(&vals[i1 + 3]);

        float2 xa0 = *reinterpret_cast<const float2*>(xb + (size_t)ca0 * D_FEAT);
        float2 xa1 = *reinterpret_cast<const float2*>(xb + (size_t)ca1 * D_FEAT);
        float2 xa2 = *reinterpret_cast<const float2*>(xb + (size_t)ca2 * D_FEAT);
        float2 xa3 = *reinterpret_cast<const float2*>(xb + (size_t)ca3 * D_FEAT);
        float2 xb0 = *reinterpret_cast<const float2*>(xb + (size_t)cb0 * D_FEAT);
        float2 xb1 = *reinterpret_cast<const float2*>(xb + (size_t)cb1 * D_FEAT);
        float2 xb2 = *reinterpret_cast<const float2*>(xb + (size_t)cb2 * D_FEAT);
        float2 xb3 = *reinterpret_cast<const float2*>(xb + (size_t)cb3 * D_FEAT);

        acc0.x = fmaf(va0, xa0.x, acc0.x); acc0.y = fmaf(va0, xa0.y, acc0.y);
        acc0.x = fmaf(va1, xa1.x, acc0.x); acc0.y = fmaf(va1, xa1.y, acc0.y);
        acc0.x = fmaf(va2, xa2.x, acc0.x); acc0.y = fmaf(va2, xa2.y, acc0.y);
        acc0.x = fmaf(va3, xa3.x, acc0.x); acc0.y = fmaf(va3, xa3.y, acc0.y);
        acc1.x = fmaf(vb0, xb0.x, acc1.x); acc1.y = fmaf(vb0, xb0.y, acc1.y);
        acc1.x = fmaf(vb1, xb1.x, acc1.x); acc1.y = fmaf(vb1, xb1.y, acc1.y);
        acc1.x = fmaf(vb2, xb2.x, acc1.x); acc1.y = fmaf(vb2, xb2.y, acc1.y);
        acc1.x = fmaf(vb3, xb3.x, acc1.x); acc1.y = fmaf(vb3, xb3.y, acc1.y);

        i0 += 4; i1 += 4;
    }

    // Finish row 0 quads.
    for (; i0 + 4 <= e0; i0 += 4) {
        int   c0 = __ldg(&col[i0 + 0]), c1 = __ldg(&col[i0 + 1]);
        int   c2 = __ldg(&col[i0 + 2]), c3 = __ldg(&col[i0 + 3]);
        float v0 = __ldg(&vals[i0 + 0]), v1 = __ldg(&vals[i0 + 1]);
        float v2 = __ldg(&vals[i0 + 2]), v3 = __ldg(&vals[i0 + 3]);
        float2 x0 = *reinterpret_cast<const float2*>(xb + (size_t)c0 * D_FEAT);
        float2 x1 = *reinterpret_cast<const float2*>(xb + (size_t)c1 * D_FEAT);
        float2 x2 = *reinterpret_cast<const float2*>(xb + (size_t)c2 * D_FEAT);
        float2 x3 = *reinterpret_cast<const float2*>(xb + (size_t)c3 * D_FEAT);
        acc0.x = fmaf(v0, x0.x, acc0.x); acc0.y = fmaf(v0, x0.y, acc0.y);
        acc0.x = fmaf(v1, x1.x, acc0.x); acc0.y = fmaf(v1, x1.y, acc0.y);
        acc0.x = fmaf(v2, x2.x, acc0.x); acc0.y = fmaf(v2, x2.y, acc0.y);
        acc0.x = fmaf(v3, x3.x, acc0.x); acc0.y = fmaf(v3, x3.y, acc0.y);
    }
    // Finish row 1 quads.
    for (; i1 + 4 <= e1; i1 += 4) {
        int   c0 = __ldg(&col[i1 + 0]), c1 = __ldg(&col[i1 + 1]);
        int   c2 = __ldg(&col[i1 + 2]), c3 = __ldg(&col[i1 + 3]);
        float v0 = __ldg(&vals[i1 + 0]), v1 = __ldg(&vals[i1 + 1]);
        float v2 = __ldg(&vals[i1 + 2]), v3 = __ldg(&vals[i1 + 3]);
        float2 x0 = *reinterpret_cast<const float2*>(xb + (size_t)c0 * D_FEAT);
        float2 x1 = *reinterpret_cast<const float2*>(xb + (size_t)c1 * D_FEAT);
        float2 x2 = *reinterpret_cast<const float2*>(xb + (size_t)c2 * D_FEAT);
        float2 x3 = *reinterpret_cast<const float2*>(xb + (size_t)c3 * D_FEAT);
        acc1.x = fmaf(v0, x0.x, acc1.x); acc1.y = fmaf(v0, x0.y, acc1.y);
        acc1.x = fmaf(v1, x1.x, acc1.x); acc1.y = fmaf(v1, x1.y, acc1.y);
        acc1.x = fmaf(v2, x2.x, acc1.x); acc1.y = fmaf(v2, x2.y, acc1.y);
        acc1.x = fmaf(v3, x3.x, acc1.x); acc1.y = fmaf(v3, x3.y, acc1.y);
    }
    // Scalar tails (interleave the two rows' remaining <=3 edges).
    for (;;) {
        bool d0 = (i0 < e0), d1 = (i1 < e1);
        if (!d0 && !d1) break;
        if (d0) {
            int c = __ldg(&col[i0]); float v = __ldg(&vals[i0]);
            float2 xv = *reinterpret_cast<const float2*>(xb + (size_t)c * D_FEAT);
            acc0.x = fmaf(v, xv.x, acc0.x); acc0.y = fmaf(v, xv.y, acc0.y);
            i0++;
        }
        if (d1) {
            int c = __ldg(&col[i1]); float v = __ldg(&vals[i1]);
            float2 xv = *reinterpret_cast<const float2*>(xb + (size_t)c * D_FEAT);
            acc1.x = fmaf(v, xv.x, acc1.x); acc1.y = fmaf(v, xv.y, acc1.y);
            i1++;
        }
    }

    int d0 = e0 - s0;
    float inv0 = 1.0f / (float)(d0 > 0 ? d0 : 1);
    *reinterpret_cast<float2*>(&out[(size_t)r0 * D_FEAT + 2 * lane]) =
        make_float2(acc0.x * inv0, acc0.y * inv0);

    if (has1) {
        int d1 = e1 - s1;
        float inv1 = 1.0f / (float)(d1 > 0 ? d1 : 1);
        *reinterpret_cast<float2*>(&out[(size_t)r1 * D_FEAT + 2 * lane]) =
            make_float2(acc1.x * inv1, acc1.y * inv1);
    }
}

extern "C" void kernel_launch(void* const* d_in, const int* in_sizes, int n_in,
                              void* d_out, int out_size) {
    const float* x    = (const float*)d_in[0];
    const float* vals = (const float*)d_in[1];
    const int*   row  = (const int*)d_in[2];
    const int*   col  = (const int*)d_in[3];
    float* out = (float*)d_out;

    int n = in_sizes[0] / D_FEAT;   // 100000
    int E = in_sizes[1];            // 1200000

    {
        int threads = 256;
        int blocks = (n + 1 + threads - 1) / threads;
        build_row_ptr<<<blocks, threads>>>(row, n, E);
    }
    {
        int threads = 256;
        int warps_per_block = threads / 32;
        int n_warps = (n + 1) / 2;      // two rows per warp
        int blocks = (n_warps + warps_per_block - 1) / warps_per_block;
        spmm_mean_2rows<<<blocks, threads>>>(x, vals, col, out, n);
    }
}

// round 6
// speedup vs baseline: 1.0881x; 1.0881x over previous
#include <cuda_runtime.h>

#define D_FEAT 64

__device__ int g_row_ptr[100001];

// Kernel A: row_ptr[r] = lower_bound(row, E, r).
__global__ void build_row_ptr(const int* __restrict__ row, int n, int E) {
    int r = blockIdx.x * blockDim.x + threadIdx.x;
    if (r > n) return;
    int lo = 0, hi = E;
    while (lo < hi) {
        int mid = (lo + hi) >> 1;
        if (__ldg(&row[mid]) < r) lo = mid + 1;
        else hi = mid;
    }
    g_row_ptr[r] = lo;
}

// Kernel B: one warp per row (R1 layout), main loop unrolled to 8 edges:
// 8 independent x-gathers (16 cache lines) in flight per warp batch.
__global__ void spmm_mean_warp_per_row(const float* __restrict__ x,
                                       const float* __restrict__ vals,
                                       const int* __restrict__ col,
                                       float* __restrict__ out,
                                       int n) {
    int warp_id = (blockIdx.x * blockDim.x + threadIdx.x) >> 5;
    int lane = threadIdx.x & 31;
    if (warp_id >= n) return;

    int s = g_row_ptr[warp_id];
    int e = g_row_ptr[warp_id + 1];

    const float* xb = x + 2 * lane;
    float2 a0 = make_float2(0.f, 0.f);
    float2 a1 = make_float2(0.f, 0.f);

    int i = s;

    // Main loop: 8 edges, 8 gathers in flight.
    for (; i + 8 <= e; i += 8) {
        int c0 = __ldg(&col[i + 0]);
        int c1 = __ldg(&col[i + 1]);
        int c2 = __ldg(&col[i + 2]);
        int c3 = __ldg(&col[i + 3]);
        int c4 = __ldg(&col[i + 4]);
        int c5 = __ldg(&col[i + 5]);
        int c6 = __ldg(&col[i + 6]);
        int c7 = __ldg(&col[i + 7]);
        float v0 = __ldg(&vals[i + 0]);
        float v1 = __ldg(&vals[i + 1]);
        float v2 = __ldg(&vals[i + 2]);
        float v3 = __ldg(&vals[i + 3]);
        float v4 = __ldg(&vals[i + 4]);
        float v5 = __ldg(&vals[i + 5]);
        float v6 = __ldg(&vals[i + 6]);
        float v7 = __ldg(&vals[i + 7]);
        float2 x0 = __ldg(reinterpret_cast<const float2*>(xb + (size_t)c0 * D_FEAT));
        float2 x1 = __ldg(reinterpret_cast<const float2*>(xb + (size_t)c1 * D_FEAT));
        float2 x2 = __ldg(reinterpret_cast<const float2*>(xb + (size_t)c2 * D_FEAT));
        float2 x3 = __ldg(reinterpret_cast<const float2*>(xb + (size_t)c3 * D_FEAT));
        float2 x4 = __ldg(reinterpret_cast<const float2*>(xb + (size_t)c4 * D_FEAT));
        float2 x5 = __ldg(reinterpret_cast<const float2*>(xb + (size_t)c5 * D_FEAT));
        float2 x6 = __ldg(reinterpret_cast<const float2*>(xb + (size_t)c6 * D_FEAT));
        float2 x7 = __ldg(reinterpret_cast<const float2*>(xb + (size_t)c7 * D_FEAT));
        a0.x = fmaf(v0, x0.x, a0.x); a0.y = fmaf(v0, x0.y, a0.y);
        a1.x = fmaf(v1, x1.x, a1.x); a1.y = fmaf(v1, x1.y, a1.y);
        a0.x = fmaf(v2, x2.x, a0.x); a0.y = fmaf(v2, x2.y, a0.y);
        a1.x = fmaf(v3, x3.x, a1.x); a1.y = fmaf(v3, x3.y, a1.y);
        a0.x = fmaf(v4, x4.x, a0.x); a0.y = fmaf(v4, x4.y, a0.y);
        a1.x = fmaf(v5, x5.x, a1.x); a1.y = fmaf(v5, x5.y, a1.y);
        a0.x = fmaf(v6, x6.x, a0.x); a0.y = fmaf(v6, x6.y, a0.y);
        a1.x = fmaf(v7, x7.x, a1.x); a1.y = fmaf(v7, x7.y, a1.y);
    }

    // Secondary: 4 edges.
    for (; i + 4 <= e; i += 4) {
        int c0 = __ldg(&col[i + 0]);
        int c1 = __ldg(&col[i + 1]);
        int c2 = __ldg(&col[i + 2]);
        int c3 = __ldg(&col[i + 3]);
        float v0 = __ldg(&vals[i + 0]);
        float v1 = __ldg(&vals[i + 1]);
        float v2 = __ldg(&vals[i + 2]);
        float v3 = __ldg(&vals[i + 3]);
        float2 x0 = __ldg(reinterpret_cast<const float2*>(xb + (size_t)c0 * D_FEAT));
        float2 x1 = __ldg(reinterpret_cast<const float2*>(xb + (size_t)c1 * D_FEAT));
        float2 x2 = __ldg(reinterpret_cast<const float2*>(xb + (size_t)c2 * D_FEAT));
        float2 x3 = __ldg(reinterpret_cast<const float2*>(xb + (size_t)c3 * D_FEAT));
        a0.x = fmaf(v0, x0.x, a0.x); a0.y = fmaf(v0, x0.y, a0.y);
        a1.x = fmaf(v1, x1.x, a1.x); a1.y = fmaf(v1, x1.y, a1.y);
        a0.x = fmaf(v2, x2.x, a0.x); a0.y = fmaf(v2, x2.y, a0.y);
        a1.x = fmaf(v3, x3.x, a1.x); a1.y = fmaf(v3, x3.y, a1.y);
    }

    // Tail: <=3 scalar edges.
    for (; i < e; i++) {
        int   c = __ldg(&col[i]);
        float v = __ldg(&vals[i]);
        float2 xv = __ldg(reinterpret_cast<const float2*>(xb + (size_t)c * D_FEAT));
        a0.x = fmaf(v, xv.x, a0.x);
        a0.y = fmaf(v, xv.y, a0.y);
    }

    int deg = e - s;
    float inv = 1.0f / (float)(deg > 0 ? deg : 1);
    float2 o = make_float2((a0.x + a1.x) * inv, (a0.y + a1.y) * inv);

    *reinterpret_cast<float2*>(&out[(size_t)warp_id * D_FEAT + 2 * lane]) = o;
}

extern "C" void kernel_launch(void* const* d_in, const int* in_sizes, int n_in,
                              void* d_out, int out_size) {
    const float* x    = (const float*)d_in[0];
    const float* vals = (const float*)d_in[1];
    const int*   row  = (const int*)d_in[2];
    const int*   col  = (const int*)d_in[3];
    float* out = (float*)d_out;

    int n = in_sizes[0] / D_FEAT;   // 100000
    int E = in_sizes[1];            // 1200000

    {
        int threads = 256;
        int blocks = (n + 1 + threads - 1) / threads;
        build_row_ptr<<<blocks, threads>>>(row, n, E);
    }
    {
        int threads = 256;
        int rows_per_block = threads / 32;
        int blocks = (n + rows_per_block - 1) / rows_per_block;
        spmm_mean_warp_per_row<<<blocks, threads>>>(x, vals, col, out, n);
    }
}